// round 12
// baseline (speedup 1.0000x reference)
#include <cuda_runtime.h>
#include <cuda_fp16.h>
#include <cstdint>

#define BATCH   32768
#define NUM_IN  256
#define NUM_HID 512
#define NUM_OUT 64
#define M_NODES 576
#define N_NODES 832
#define KFAN    32
#define COLS    64             // batch columns per block (32 half2 words)
#define WPN     32             // u32 words per node row
#define THREADS 512            // 16 warps
#define SLOTS   16             // nodes per round (1 per warp)
#define RSTRIDE 800            // words/round: 256 src16 + 512 w_h2 + 16 bias + 16 tgt
#define RMAX    576
#define DUMMY   576            // dummy pred index, level pinned 0

// round-major param blob, per round r at r*RSTRIDE:
//   [0..256)   src16: two u16 (pred*WPN) word-offsets per u32 (slot*16 + j)
//   [256..768) w_h2:  u32 = half2 {w,w}
//   [768..784) bias per slot (f32)
//   [784..800) target word-offset per slot (int), -1 = dummy
__device__ float g_blob[(size_t)RMAX * RSTRIDE];
__device__ int   g_sched[RMAX * SLOTS];
__device__ int   g_nrounds;
__device__ int   g_ready;

// ---------------------------------------------------------------------------
// Reset kernel: clears the ready flag each replay (stream-ordered).
// ---------------------------------------------------------------------------
__global__ void reset_kernel() { g_ready = 0; }

// ---------------------------------------------------------------------------
// SMEM layouts
// ---------------------------------------------------------------------------
#define ST_WORDS    (N_NODES * WPN)                // 26624 u32
#define STAGE_WORDS 2112                           // 64x33 f32 staging >= 2*RSTRIDE
#define TOTAL_WORDS (ST_WORDS + STAGE_WORDS)       // 28736 -> 114944 B

extern __shared__ float smem_f[];

__device__ __forceinline__ void cp16(void* sdst, const void* gsrc) {
    uint32_t s = (uint32_t)__cvta_generic_to_shared(sdst);
    asm volatile("cp.async.cg.shared.global [%0], [%1], 16;\n" :: "r"(s), "l"(gsrc));
}

__device__ __forceinline__ __half2 u2h(uint32_t u) { return *(__half2*)&u; }

// ---------------------------------------------------------------------------
// Block-0 prologue: ASAP levels (chunked Gauss-Seidel over smem pred lists,
// 512 threads covering 576 nodes) -> counting-sort into 16-slot rounds ->
// fill g_blob. Then publish g_ready.
// ---------------------------------------------------------------------------
__device__ void schedule_and_fill(const float* __restrict__ w,
                                  const float* __restrict__ bias,
                                  const int*   __restrict__ src) {
    unsigned short* plist = (unsigned short*)smem_f;          // 576*32 u16 = 9216 f
    int* lev   = (int*)(smem_f + 9216);                       // [DUMMY+1]
    int* cnt   = lev + (DUMMY + 1);                           // [M_NODES+1]
    int* rbase = cnt + (M_NODES + 1);
    int* pos   = rbase + (M_NODES + 1);
    int* misc  = pos + (M_NODES + 1);                         // [0]=lmax [1]=R

    const int tid = threadIdx.x;

    // pred lists into smem (node-space t-index, DUMMY for inputs)
    for (int i = tid; i < M_NODES * KFAN; i += THREADS) {
        int s = src[i];
        plist[i] = (unsigned short)((s >= NUM_IN) ? (s - NUM_IN) : DUMMY);
    }
    for (int i = tid; i <= DUMMY; i += THREADS) lev[i] = 0;
    for (int i = tid; i <= M_NODES; i += THREADS) { cnt[i] = 0; pos[i] = 0; }
    if (tid == 0) misc[0] = 0;
    __syncthreads();

    // 9 chunks of 64 consecutive nodes; preds strictly lower-indexed.
    for (int c = 0; c < M_NODES / 64; c++) {
        const bool mine = ((tid >> 6) == (c & 7)) && (c < 8 ? true : tid < 64);
        const int  n    = c * 64 + (tid & 63);
        while (true) {
            int ch = 0;
            if (mine) {
                int m = 0;
                #pragma unroll 8
                for (int k = 0; k < KFAN; k++) {
                    int l = lev[plist[n * KFAN + k]];
                    m = (l > m) ? l : m;
                }
                if (m + 1 != lev[n]) { lev[n] = m + 1; ch = 1; }
            }
            if (!__syncthreads_or(ch)) break;
        }
    }

    // histogram + lmax (threads cover 576 nodes)
    for (int n = tid; n < M_NODES; n += THREADS) {
        atomicAdd(&cnt[lev[n]], 1);
        atomicMax(&misc[0], lev[n]);
    }
    __syncthreads();

    if (tid == 0) {
        int r = 0, lmax = misc[0];
        for (int L = 1; L <= lmax; L++) { rbase[L] = r; r += (cnt[L] + SLOTS - 1) >> 4; }
        misc[1] = r;
        g_nrounds = r;
    }
    __syncthreads();
    const int R = misc[1];

    for (int i = tid; i < R * SLOTS; i += THREADS) g_sched[i] = -1;
    __syncthreads();

    for (int n = tid; n < M_NODES; n += THREADS) {
        int L = lev[n];
        int q = atomicAdd(&pos[L], 1);
        g_sched[(rbase[L] + (q >> 4)) * SLOTS + (q & 15)] = n;
    }
    __syncthreads();

    // ---- blob fill (reads g_sched written by this block: same-SM coherent) ----
    // src16
    for (int u = tid; u < R * SLOTS * 16; u += THREADS) {
        int slot = u >> 4, j = u & 15;
        int nd = g_sched[slot];
        int r = slot >> 4, s = slot & 15;
        unsigned v = 0;
        if (nd >= 0) {
            unsigned a = (unsigned)src[nd * KFAN + 2 * j] * WPN;
            unsigned b = (unsigned)src[nd * KFAN + 2 * j + 1] * WPN;
            v = (a & 0xFFFFu) | (b << 16);
        }
        ((unsigned*)g_blob)[(size_t)r * RSTRIDE + s * 16 + j] = v;
    }
    // w_h2
    for (int u = tid; u < R * SLOTS * 32; u += THREADS) {
        int slot = u >> 5, k = u & 31;
        int nd = g_sched[slot];
        int r = slot >> 4, s = slot & 15;
        float wv = (nd >= 0) ? w[nd * KFAN + k] : 0.0f;
        __half2 h2 = __half2half2(__float2half_rn(wv));
        ((uint32_t*)g_blob)[(size_t)r * RSTRIDE + 256 + s * 32 + k] = *(uint32_t*)&h2;
    }
    // bias + target
    for (int u = tid; u < R * SLOTS; u += THREADS) {
        int nd = g_sched[u];
        int r = u >> 4, s = u & 15;
        g_blob[(size_t)r * RSTRIDE + 768 + s] = (nd >= 0) ? bias[nd] : 0.0f;
        ((int*)g_blob)[(size_t)r * RSTRIDE + 784 + s] = (nd >= 0) ? (NUM_IN + nd) * WPN : -1;
    }

    __threadfence();
    __syncthreads();
    if (tid == 0) atomicExch(&g_ready, 1);
}

// ---------------------------------------------------------------------------
// Fused kernel: grid 513. Block 0 = scheduler/producer; blocks 1..512 =
// column blocks (2 per SM): transpose -> spin on g_ready -> HFMA2 rounds.
// ---------------------------------------------------------------------------
__global__ __launch_bounds__(THREADS, 2)
void neat_main_kernel(const float* __restrict__ x,
                      float* __restrict__ out,
                      const float* __restrict__ w,
                      const float* __restrict__ bias,
                      const int*   __restrict__ src) {
    if (blockIdx.x == 0) {
        schedule_and_fill(w, bias, src);
        return;
    }

    uint32_t* st   = (uint32_t*)smem_f;            // [N_NODES][WPN] half2 words
    float*   stage = smem_f + ST_WORDS;

    const int tid  = threadIdx.x;
    const int wid  = tid >> 5;
    const int lane = tid & 31;
    const int b0   = (blockIdx.x - 1) * COLS;

    // ---- input: x[b][n] f32 -> st[n] half2-packed; 8 chunks of 32 inputs ----
    for (int ch = 0; ch < 8; ch++) {
        const int nc0 = ch * 32;
        __syncthreads();
        #pragma unroll
        for (int i = 0; i < 4; i++) {
            int idx = tid + i * THREADS;           // 2048 = 64 rows x 32 cols
            int row = idx >> 5, c = idx & 31;
            stage[row * 33 + c] = x[(size_t)(b0 + row) * NUM_IN + nc0 + c];
        }
        __syncthreads();
        #pragma unroll
        for (int i = 0; i < 2; i++) {
            int idx = tid + i * THREADS;           // 1024 = 32 nodes x 32 words
            int n = idx >> 5, wc = idx & 31;
            float lo = stage[(2 * wc) * 33 + n];
            float hi = stage[(2 * wc + 1) * 33 + n];
            __half2 h = __floats2half2_rn(lo, hi);
            st[(nc0 + n) * WPN + wc] = *(uint32_t*)&h;
        }
    }
    __syncthreads();

    // ---- wait for block 0 to publish the schedule ----
    if (tid == 0) {
        while (atomicAdd(&g_ready, 0) == 0) __nanosleep(128);
    }
    __syncthreads();
    const int R = *(volatile int*)&g_nrounds;

    // ---- prefetch round 0 params ----
    if (tid < RSTRIDE / 4) cp16(stage + tid * 4, g_blob + tid * 4);
    asm volatile("cp.async.commit_group;\n");
    asm volatile("cp.async.wait_group 0;\n" ::: "memory");
    __syncthreads();

    uint32_t* stc = st + lane;                     // lane owns cols (2l, 2l+1)

    // ---- main rounds: warp wid evaluates slot wid over 64 columns ----
    for (int r = 0; r < R; r++) {
        float* P  = stage + (r & 1) * RSTRIDE;
        float* Pn = stage + ((r + 1) & 1) * RSTRIDE;
        if (r + 1 < R && tid < RSTRIDE / 4)
            cp16(Pn + tid * 4, g_blob + (size_t)(r + 1) * RSTRIDE + tid * 4);
        asm volatile("cp.async.commit_group;\n");

        const int tgt = ((const int*)P)[784 + wid];
        if (tgt >= 0) {
            const uint4* s4 = (const uint4*)((const unsigned*)P + wid * 16);
            const uint4* w4 = (const uint4*)((const uint32_t*)P + 256 + wid * 32);
            const float  bt = P[768 + wid];

            float z0 = bt, z1 = bt;
            #pragma unroll
            for (int half = 0; half < 2; half++) { // 16 preds per flush group
                __half2 A = __float2half2_rn(0.f);
                __half2 B = __float2half2_rn(0.f);
                __half2 C = __float2half2_rn(0.f);
                __half2 D = __float2half2_rn(0.f);
                #pragma unroll
                for (int h = 0; h < 2; h++) {      // 8 preds per iter
                    uint4 u  = s4[half * 2 + h];
                    uint4 wa = w4[half * 4 + h * 2];
                    uint4 wb = w4[half * 4 + h * 2 + 1];
                    uint32_t v0 = stc[u.x & 0xFFFFu];
                    uint32_t v1 = stc[u.x >> 16];
                    uint32_t v2 = stc[u.y & 0xFFFFu];
                    uint32_t v3 = stc[u.y >> 16];
                    uint32_t v4 = stc[u.z & 0xFFFFu];
                    uint32_t v5 = stc[u.z >> 16];
                    uint32_t v6 = stc[u.w & 0xFFFFu];
                    uint32_t v7 = stc[u.w >> 16];
                    A = __hfma2(u2h(v0), u2h(wa.x), A);
                    B = __hfma2(u2h(v1), u2h(wa.y), B);
                    C = __hfma2(u2h(v2), u2h(wa.z), C);
                    D = __hfma2(u2h(v3), u2h(wa.w), D);
                    A = __hfma2(u2h(v4), u2h(wb.x), A);
                    B = __hfma2(u2h(v5), u2h(wb.y), B);
                    C = __hfma2(u2h(v6), u2h(wb.z), C);
                    D = __hfma2(u2h(v7), u2h(wb.w), D);
                }
                __half2 s = __hadd2(__hadd2(A, B), __hadd2(C, D));
                float2  f = __half22float2(s);
                z0 += f.x;
                z1 += f.y;
            }
            float o0 = __fdividef(1.0f, 1.0f + __expf(-z0));
            float o1 = __fdividef(1.0f, 1.0f + __expf(-z1));
            __half2 hres = __floats2half2_rn(o0, o1);
            stc[tgt] = *(uint32_t*)&hres;
        }

        asm volatile("cp.async.wait_group 0;\n" ::: "memory");
        __syncthreads();
    }

    // ---- output: out[b][j] f32; 2 chunks of 32 output nodes ----
    for (int ch = 0; ch < 2; ch++) {
        const int j0 = ch * 32;
        __syncthreads();
        #pragma unroll
        for (int i = 0; i < 2; i++) {
            int idx = tid + i * THREADS;           // 1024 = 32 j x 32 words
            int j = idx >> 5, wc = idx & 31;
            uint32_t u = st[(NUM_IN + NUM_HID + j0 + j) * WPN + wc];
            float2 v = __half22float2(*(__half2*)&u);
            stage[(2 * wc) * 33 + j]     = v.x;
            stage[(2 * wc + 1) * 33 + j] = v.y;
        }
        __syncthreads();
        #pragma unroll
        for (int i = 0; i < 4; i++) {
            int idx = tid + i * THREADS;           // 2048 = 64 rows x 32 j
            int row = idx >> 5, j = idx & 31;
            out[(size_t)(b0 + row) * NUM_OUT + j0 + j] = stage[row * 33 + j];
        }
    }
}

// ---------------------------------------------------------------------------
extern "C" void kernel_launch(void* const* d_in, const int* in_sizes, int n_in,
                              void* d_out, int out_size) {
    const float* x    = (const float*)d_in[0];
    const float* w    = (const float*)d_in[1];
    const float* bias = (const float*)d_in[2];
    const int*   src  = (const int*)d_in[3];
    float* out = (float*)d_out;
    (void)in_sizes; (void)n_in; (void)out_size;

    cudaFuncSetAttribute(neat_main_kernel,
                         cudaFuncAttributeMaxDynamicSharedMemorySize,
                         TOTAL_WORDS * 4);

    reset_kernel<<<1, 1>>>();
    neat_main_kernel<<<BATCH / COLS + 1, THREADS, TOTAL_WORDS * 4>>>(x, out, w, bias, src);
}

// round 13
// speedup vs baseline: 1.0106x; 1.0106x over previous
#include <cuda_runtime.h>
#include <cuda_fp16.h>
#include <cstdint>

#define BATCH   32768
#define NUM_IN  256
#define NUM_HID 512
#define NUM_OUT 64
#define M_NODES 576
#define N_NODES 832
#define KFAN    32
#define COLS    64             // batch columns per block (32 half2 words)
#define WPN     32             // u32 words per node row
#define THREADS 512            // 16 warps
#define SLOTS   16             // nodes per round (1 per warp)
#define RSTRIDE 800            // words/round: 256 src16 + 512 w_h2 + 16 bias + 16 tgt
#define RMAX    576
#define DUMMY   576            // dummy pred index, level pinned 0

// round-major param blob, per round r at r*RSTRIDE:
//   [0..256)   src16: two u16 (pred*WPN) word-offsets per u32 (slot*16 + j)
//   [256..768) w_h2:  u32 = half2 {w,w}
//   [768..784) bias per slot (f32)
//   [784..800) target word-offset per slot (int), -1 = dummy
__device__ float g_blob[(size_t)RMAX * RSTRIDE];
__device__ int   g_sched[RMAX * SLOTS];
__device__ int   g_nrounds;

// ---------------------------------------------------------------------------
// Kernel A: ASAP levels via chunked Gauss-Seidel (preds in registers,
// DUMMY-padded), one fused barrier per pass via __syncthreads_or;
// then counting-sort levels into rounds of <= SLOTS.  (R11-proven, 33 us)
// ---------------------------------------------------------------------------
__global__ __launch_bounds__(M_NODES)
void schedule_kernel(const int* __restrict__ src) {
    __shared__ int lev[DUMMY + 32];       // lev[DUMMY..] pinned 0
    __shared__ int cnt[M_NODES + 1];
    __shared__ int rbase[M_NODES + 1];
    __shared__ int pos[M_NODES + 1];
    __shared__ int lmax, R_sh;

    const int t = threadIdx.x;

    int p[KFAN];
    #pragma unroll
    for (int k = 0; k < KFAN; k++) {
        int s = src[t * KFAN + k];
        p[k] = (s >= NUM_IN) ? (s - NUM_IN) : DUMMY;
    }
    lev[t] = 0;
    if (t < 32) lev[DUMMY + t] = 0;
    for (int i = t; i <= M_NODES; i += M_NODES) { cnt[i] = 0; pos[i] = 0; }
    if (t == 0) lmax = 0;
    __syncthreads();

    for (int c = 0; c < M_NODES / 64; c++) {
        const bool mine = ((t >> 6) == c);
        while (true) {
            int ch = 0;
            if (mine) {
                int m = 0;
                #pragma unroll
                for (int k = 0; k < KFAN; k++) {
                    int l = lev[p[k]];
                    m = (l > m) ? l : m;
                }
                if (m + 1 != lev[t]) { lev[t] = m + 1; ch = 1; }
            }
            if (!__syncthreads_or(ch)) break;
        }
    }

    atomicAdd(&cnt[lev[t]], 1);
    atomicMax(&lmax, lev[t]);
    __syncthreads();

    if (t == 0) {
        int r = 0;
        for (int L = 1; L <= lmax; L++) { rbase[L] = r; r += (cnt[L] + SLOTS - 1) >> 4; }
        R_sh = r;
        g_nrounds = r;
    }
    __syncthreads();

    for (int i = t; i < R_sh * SLOTS; i += M_NODES) g_sched[i] = -1;
    __syncthreads();

    {
        int L = lev[t];
        int q = atomicAdd(&pos[L], 1);
        g_sched[(rbase[L] + (q >> 4)) * SLOTS + (q & 15)] = t;
    }
}

// ---------------------------------------------------------------------------
// Kernel B: grid-parallel blob fill, one block per (used) round.
// ---------------------------------------------------------------------------
__global__ __launch_bounds__(256)
void blob_fill_kernel(const int* __restrict__ src,
                      const float* __restrict__ w,
                      const float* __restrict__ bias) {
    const int r = blockIdx.x;
    if (r >= g_nrounds) return;
    float* Pr = g_blob + (size_t)r * RSTRIDE;
    const int tid = threadIdx.x;

    {   // src16: premultiplied (pred * WPN) offsets
        int slot = tid >> 4, j = tid & 15;
        int nd = g_sched[r * SLOTS + slot];
        unsigned v = 0;
        if (nd >= 0) {
            unsigned a = (unsigned)src[nd * KFAN + 2 * j] * WPN;
            unsigned b = (unsigned)src[nd * KFAN + 2 * j + 1] * WPN;
            v = (a & 0xFFFFu) | (b << 16);
        }
        ((unsigned*)Pr)[slot * 16 + j] = v;
    }
    #pragma unroll
    for (int u = 0; u < 2; u++) {
        int q = tid + u * 256;
        int slot = q >> 5, k = q & 31;
        int nd = g_sched[r * SLOTS + slot];
        float wv = (nd >= 0) ? w[nd * KFAN + k] : 0.0f;
        __half2 h2 = __half2half2(__float2half_rn(wv));
        ((uint32_t*)Pr)[256 + slot * 32 + k] = *(uint32_t*)&h2;
    }
    if (tid < SLOTS) {
        int nd = g_sched[r * SLOTS + tid];
        Pr[768 + tid] = (nd >= 0) ? bias[nd] : 0.0f;
        ((int*)Pr)[784 + tid] = (nd >= 0) ? (NUM_IN + nd) * WPN : -1;
    }
}

// ---------------------------------------------------------------------------
// Main kernel: 512 blocks x 512 threads, 2 blocks/SM. State half2-packed in
// SMEM; HFMA2 inner product. Params TRIPLE-buffered via cp.async with
// wait_group 1 (round r+1's fetch has a full round of slack).
// ---------------------------------------------------------------------------
#define ST_WORDS    (N_NODES * WPN)                // 26624 u32
#define STAGE_WORDS (3 * RSTRIDE)                  // 2400 (covers 64x33=2112 staging)
#define TOTAL_WORDS (ST_WORDS + STAGE_WORDS)       // 29024 -> 116096 B

extern __shared__ float smem_f[];

__device__ __forceinline__ void cp16(void* sdst, const void* gsrc) {
    uint32_t s = (uint32_t)__cvta_generic_to_shared(sdst);
    asm volatile("cp.async.cg.shared.global [%0], [%1], 16;\n" :: "r"(s), "l"(gsrc));
}

__device__ __forceinline__ __half2 u2h(uint32_t u) { return *(__half2*)&u; }

__global__ __launch_bounds__(THREADS, 2)
void neat_main_kernel(const float* __restrict__ x,
                      float* __restrict__ out) {
    uint32_t* st   = (uint32_t*)smem_f;            // [N_NODES][WPN] half2 words
    float*   stage = smem_f + ST_WORDS;            // 3-buffer params / staging

    const int tid  = threadIdx.x;
    const int wid  = tid >> 5;
    const int lane = tid & 31;
    const int b0   = blockIdx.x * COLS;
    const int R    = g_nrounds;

    // ---- input: x[b][n] f32 -> st[n] half2-packed; 8 chunks of 32 inputs ----
    for (int ch = 0; ch < 8; ch++) {
        const int nc0 = ch * 32;
        __syncthreads();
        #pragma unroll
        for (int i = 0; i < 4; i++) {
            int idx = tid + i * THREADS;           // 2048 = 64 rows x 32 cols
            int row = idx >> 5, c = idx & 31;
            stage[row * 33 + c] = x[(size_t)(b0 + row) * NUM_IN + nc0 + c];
        }
        __syncthreads();
        #pragma unroll
        for (int i = 0; i < 2; i++) {
            int idx = tid + i * THREADS;           // 1024 = 32 nodes x 32 words
            int n = idx >> 5, wc = idx & 31;
            float lo = stage[(2 * wc) * 33 + n];
            float hi = stage[(2 * wc + 1) * 33 + n];
            __half2 h = __floats2half2_rn(lo, hi);
            st[(nc0 + n) * WPN + wc] = *(uint32_t*)&h;
        }
    }
    __syncthreads();

    // ---- prime the 3-deep param pipeline: rounds 0 and 1 ----
    if (tid < RSTRIDE / 4) cp16(stage + tid * 4, g_blob + tid * 4);
    asm volatile("cp.async.commit_group;\n");
    if (R > 1 && tid < RSTRIDE / 4)
        cp16(stage + RSTRIDE + tid * 4, g_blob + (size_t)RSTRIDE + tid * 4);
    asm volatile("cp.async.commit_group;\n");
    asm volatile("cp.async.wait_group 1;\n" ::: "memory");   // round 0 done
    __syncthreads();

    uint32_t* stc = st + lane;                     // lane owns cols (2l, 2l+1)

    // ---- main rounds: warp wid evaluates slot wid over 64 columns ----
    // invariant at loop top: buf[r%3] ready+visible; buf[(r+1)%3] in flight.
    for (int r = 0; r < R; r++) {
        float* P = stage + (r % 3) * RSTRIDE;

        // prefetch round r+2 into the buffer freed by round r-1
        if (r + 2 < R && tid < RSTRIDE / 4)
            cp16(stage + ((r + 2) % 3) * RSTRIDE + tid * 4,
                 g_blob + (size_t)(r + 2) * RSTRIDE + tid * 4);
        asm volatile("cp.async.commit_group;\n");  // commit (possibly empty)

        const int tgt = ((const int*)P)[784 + wid];
        if (tgt >= 0) {
            const uint4* s4 = (const uint4*)((const unsigned*)P + wid * 16);
            const uint4* w4 = (const uint4*)((const uint32_t*)P + 256 + wid * 32);
            const float  bt = P[768 + wid];

            float z0 = bt, z1 = bt;
            #pragma unroll
            for (int half = 0; half < 2; half++) { // 16 preds per flush group
                __half2 A = __float2half2_rn(0.f);
                __half2 B = __float2half2_rn(0.f);
                __half2 C = __float2half2_rn(0.f);
                __half2 D = __float2half2_rn(0.f);
                #pragma unroll
                for (int h = 0; h < 2; h++) {      // 8 preds per iter
                    uint4 u  = s4[half * 2 + h];
                    uint4 wa = w4[half * 4 + h * 2];
                    uint4 wb = w4[half * 4 + h * 2 + 1];
                    uint32_t v0 = stc[u.x & 0xFFFFu];
                    uint32_t v1 = stc[u.x >> 16];
                    uint32_t v2 = stc[u.y & 0xFFFFu];
                    uint32_t v3 = stc[u.y >> 16];
                    uint32_t v4 = stc[u.z & 0xFFFFu];
                    uint32_t v5 = stc[u.z >> 16];
                    uint32_t v6 = stc[u.w & 0xFFFFu];
                    uint32_t v7 = stc[u.w >> 16];
                    A = __hfma2(u2h(v0), u2h(wa.x), A);
                    B = __hfma2(u2h(v1), u2h(wa.y), B);
                    C = __hfma2(u2h(v2), u2h(wa.z), C);
                    D = __hfma2(u2h(v3), u2h(wa.w), D);
                    A = __hfma2(u2h(v4), u2h(wb.x), A);
                    B = __hfma2(u2h(v5), u2h(wb.y), B);
                    C = __hfma2(u2h(v6), u2h(wb.z), C);
                    D = __hfma2(u2h(v7), u2h(wb.w), D);
                }
                __half2 s = __hadd2(__hadd2(A, B), __hadd2(C, D));
                float2  f = __half22float2(s);
                z0 += f.x;
                z1 += f.y;
            }
            float o0 = __fdividef(1.0f, 1.0f + __expf(-z0));
            float o1 = __fdividef(1.0f, 1.0f + __expf(-z1));
            __half2 hres = __floats2half2_rn(o0, o1);
            stc[tgt] = *(uint32_t*)&hres;
        }

        // complete round r+1's fetch (committed a full round ago); leave
        // round r+2's group in flight.
        asm volatile("cp.async.wait_group 1;\n" ::: "memory");
        __syncthreads();
    }

    // ---- output: out[b][j] f32; 2 chunks of 32 output nodes ----
    for (int ch = 0; ch < 2; ch++) {
        const int j0 = ch * 32;
        __syncthreads();
        #pragma unroll
        for (int i = 0; i < 2; i++) {
            int idx = tid + i * THREADS;           // 1024 = 32 j x 32 words
            int j = idx >> 5, wc = idx & 31;
            uint32_t u = st[(NUM_IN + NUM_HID + j0 + j) * WPN + wc];
            float2 v = __half22float2(*(__half2*)&u);
            stage[(2 * wc) * 33 + j]     = v.x;
            stage[(2 * wc + 1) * 33 + j] = v.y;
        }
        __syncthreads();
        #pragma unroll
        for (int i = 0; i < 4; i++) {
            int idx = tid + i * THREADS;           // 2048 = 64 rows x 32 j
            int row = idx >> 5, j = idx & 31;
            out[(size_t)(b0 + row) * NUM_OUT + j0 + j] = stage[row * 33 + j];
        }
    }
}

// ---------------------------------------------------------------------------
extern "C" void kernel_launch(void* const* d_in, const int* in_sizes, int n_in,
                              void* d_out, int out_size) {
    const float* x    = (const float*)d_in[0];
    const float* w    = (const float*)d_in[1];
    const float* bias = (const float*)d_in[2];
    const int*   src  = (const int*)d_in[3];
    float* out = (float*)d_out;
    (void)in_sizes; (void)n_in; (void)out_size;

    cudaFuncSetAttribute(neat_main_kernel,
                         cudaFuncAttributeMaxDynamicSharedMemorySize,
                         TOTAL_WORDS * 4);

    schedule_kernel<<<1, M_NODES>>>(src);
    blob_fill_kernel<<<RMAX, 256>>>(src, w, bias);
    neat_main_kernel<<<BATCH / COLS, THREADS, TOTAL_WORDS * 4>>>(x, out);
}

// round 14
// speedup vs baseline: 1.1180x; 1.1063x over previous
#include <cuda_runtime.h>
#include <cuda_fp16.h>
#include <cstdint>

#define BATCH   32768
#define NUM_IN  256
#define NUM_HID 512
#define NUM_OUT 64
#define M_NODES 576
#define N_NODES 832
#define KFAN    32
#define COLS    64             // batch columns per block (32 half2 words)
#define WPN     32             // u32 words per node row
#define THREADS 512            // 16 warps
#define NWARP   16
#define NSTRIDE 52             // words per node: 16 src16 + 32 w_h2 + bias + tgt + 2 pad
#define DUMMY   576            // dummy pred index, level pinned 0
#define MAXLVL  288            // max supported DAG depth (actual ~40)

// node-major param blob, position i (level-major order) at i*NSTRIDE:
//   [0..16)  src16: two u16 (pred*WPN) word-offsets per u32
//   [16..48) w_h2:  u32 = half2 {w,w}
//   [48]     bias (f32)
//   [49]     target word-offset (int)
__device__ float g_params[(size_t)M_NODES * NSTRIDE];
__device__ int   g_order[M_NODES];      // position -> node t-index
__device__ int   g_lw[MAXLVL];          // level widths (0-indexed)
__device__ int   g_nlevels;

// ---------------------------------------------------------------------------
// Kernel A: ASAP levels via chunked Gauss-Seidel (R11-proven), then
// counting-sort nodes into level-major order + level width table.
// ---------------------------------------------------------------------------
__global__ __launch_bounds__(M_NODES)
void schedule_kernel(const int* __restrict__ src) {
    __shared__ int lev[DUMMY + 32];       // lev[DUMMY..] pinned 0
    __shared__ int cnt[M_NODES + 1];
    __shared__ int lbase[M_NODES + 1];
    __shared__ int pos[M_NODES + 1];
    __shared__ int lmax;

    const int t = threadIdx.x;

    int p[KFAN];
    #pragma unroll
    for (int k = 0; k < KFAN; k++) {
        int s = src[t * KFAN + k];
        p[k] = (s >= NUM_IN) ? (s - NUM_IN) : DUMMY;
    }
    lev[t] = 0;
    if (t < 32) lev[DUMMY + t] = 0;
    for (int i = t; i <= M_NODES; i += M_NODES) { cnt[i] = 0; pos[i] = 0; }
    if (t == 0) lmax = 0;
    __syncthreads();

    for (int c = 0; c < M_NODES / 64; c++) {
        const bool mine = ((t >> 6) == c);
        while (true) {
            int ch = 0;
            if (mine) {
                int m = 0;
                #pragma unroll
                for (int k = 0; k < KFAN; k++) {
                    int l = lev[p[k]];
                    m = (l > m) ? l : m;
                }
                if (m + 1 != lev[t]) { lev[t] = m + 1; ch = 1; }
            }
            if (!__syncthreads_or(ch)) break;
        }
    }

    atomicAdd(&cnt[lev[t]], 1);
    atomicMax(&lmax, lev[t]);
    __syncthreads();

    if (t == 0) {
        int acc = 0;
        for (int L = 1; L <= lmax; L++) { lbase[L] = acc; acc += cnt[L]; }
        g_nlevels = lmax;
    }
    __syncthreads();

    if (t < lmax) g_lw[t] = cnt[t + 1];            // level L (1-based) -> slot L-1

    {
        int L = lev[t];
        int q = atomicAdd(&pos[L], 1);
        g_order[lbase[L] + q] = t;
    }
}

// ---------------------------------------------------------------------------
// Kernel B: node-major param fill — one block per node position.
// ---------------------------------------------------------------------------
__global__ __launch_bounds__(64)
void blob_fill_kernel(const int* __restrict__ src,
                      const float* __restrict__ w,
                      const float* __restrict__ bias) {
    const int i  = blockIdx.x;
    const int nd = g_order[i];
    float* Pn = g_params + (size_t)i * NSTRIDE;
    const int tid = threadIdx.x;

    if (tid < 16) {                                // src16: premultiplied offsets
        unsigned a = (unsigned)src[nd * KFAN + 2 * tid] * WPN;
        unsigned b = (unsigned)src[nd * KFAN + 2 * tid + 1] * WPN;
        ((unsigned*)Pn)[tid] = (a & 0xFFFFu) | (b << 16);
    } else if (tid < 48) {                         // w_h2
        int k = tid - 16;
        __half2 h2 = __half2half2(__float2half_rn(w[nd * KFAN + k]));
        ((uint32_t*)Pn)[16 + k] = *(uint32_t*)&h2;
    } else if (tid == 48) {
        Pn[48] = bias[nd];
    } else if (tid == 49) {
        ((int*)Pn)[49] = (NUM_IN + nd) * WPN;
    } else if (tid < 52) {
        Pn[tid] = 0.0f;
    }
}

// ---------------------------------------------------------------------------
// Main kernel: 512 blocks x 512 threads, 2 blocks/SM (smem identical to R11).
// Per-warp double-buffered param pipeline (cp.async + warp-local wait);
// block barrier only at level boundaries.
// ---------------------------------------------------------------------------
#define ST_WORDS    (N_NODES * WPN)                // 26624 u32
#define STAGE_WORDS 2112                           // transpose staging / params+lw
#define TOTAL_WORDS (ST_WORDS + STAGE_WORDS)       // 28736 -> 114944 B (= R11)
// within stage: [0..1664) = 16 warps x 2 bufs x 52 words ; [1664..1952) = lw

extern __shared__ float smem_f[];

__device__ __forceinline__ void cp16(void* sdst, const void* gsrc) {
    uint32_t s = (uint32_t)__cvta_generic_to_shared(sdst);
    asm volatile("cp.async.cg.shared.global [%0], [%1], 16;\n" :: "r"(s), "l"(gsrc));
}

__device__ __forceinline__ __half2 u2h(uint32_t u) { return *(__half2*)&u; }

__global__ __launch_bounds__(THREADS, 2)
void neat_main_kernel(const float* __restrict__ x,
                      float* __restrict__ out) {
    uint32_t* st   = (uint32_t*)smem_f;            // [N_NODES][WPN] half2 words
    float*   stage = smem_f + ST_WORDS;
    int*     lw_s  = (int*)(stage + 1664);         // [MAXLVL] level widths

    const int tid  = threadIdx.x;
    const int wid  = tid >> 5;
    const int lane = tid & 31;
    const int b0   = blockIdx.x * COLS;
    const int nl   = g_nlevels;

    // ---- input: x[b][n] f32 -> st[n] half2-packed; 8 chunks of 32 inputs ----
    for (int ch = 0; ch < 8; ch++) {
        const int nc0 = ch * 32;
        __syncthreads();
        #pragma unroll
        for (int i = 0; i < 4; i++) {
            int idx = tid + i * THREADS;           // 2048 = 64 rows x 32 cols
            int row = idx >> 5, c = idx & 31;
            stage[row * 33 + c] = x[(size_t)(b0 + row) * NUM_IN + nc0 + c];
        }
        __syncthreads();
        #pragma unroll
        for (int i = 0; i < 2; i++) {
            int idx = tid + i * THREADS;           // 1024 = 32 nodes x 32 words
            int n = idx >> 5, wc = idx & 31;
            float lo = stage[(2 * wc) * 33 + n];
            float hi = stage[(2 * wc + 1) * 33 + n];
            __half2 h = __floats2half2_rn(lo, hi);
            st[(nc0 + n) * WPN + wc] = *(uint32_t*)&h;
        }
    }
    __syncthreads();                               // staging free, lw loadable

    for (int i = tid; i < nl; i += THREADS) lw_s[i] = g_lw[i];
    __syncthreads();                               // lw visible to all warps

    float* mybuf = stage + wid * 2 * NSTRIDE;      // this warp's double buffer

    // per-warp prefetch iterator over (level-major) node positions
    int pL = 0, pi = wid, pbase = 0;
    auto it_next = [&]() -> int {
        while (pL < nl && pi >= lw_s[pL]) { pbase += lw_s[pL]; pL++; pi = wid; }
        if (pL >= nl) return -1;
        int r = pbase + pi;
        pi += NWARP;
        return r;
    };
    auto fetch = [&](int npos, int b) {
        if (lane < NSTRIDE / 4)
            cp16(mybuf + b * NSTRIDE + lane * 4,
                 g_params + (size_t)npos * NSTRIDE + lane * 4);
    };

    // prime: fetch this warp's first node
    {
        int np = it_next();
        if (np >= 0) fetch(np, 0);
    }
    asm volatile("cp.async.commit_group;\n");

    uint32_t* stc = st + lane;                     // lane owns cols (2l, 2l+1)
    int buf = 0;

    // ---- main: levels; warps decoupled within a level ----
    for (int L = 0; L < nl; L++) {
        const int wL = lw_s[L];
        for (int i = wid; i < wL; i += NWARP) {
            asm volatile("cp.async.wait_group 0;\n" ::: "memory");
            __syncwarp();
            // start next fetch (overlaps this node's compute)
            {
                int np = it_next();
                if (np >= 0) fetch(np, buf ^ 1);
            }
            asm volatile("cp.async.commit_group;\n");

            const float* P  = mybuf + buf * NSTRIDE;
            const uint4* s4 = (const uint4*)P;             // 16 src16 words
            const uint4* w4 = (const uint4*)((const uint32_t*)P + 16);
            const float  bt = P[48];
            const int   tgt = ((const int*)P)[49];

            float z0 = bt, z1 = bt;
            #pragma unroll
            for (int half = 0; half < 2; half++) {         // 16 preds per flush
                __half2 A = __float2half2_rn(0.f);
                __half2 B = __float2half2_rn(0.f);
                __half2 C = __float2half2_rn(0.f);
                __half2 D = __float2half2_rn(0.f);
                #pragma unroll
                for (int h = 0; h < 2; h++) {              // 8 preds per iter
                    uint4 u  = s4[half * 2 + h];
                    uint4 wa = w4[half * 4 + h * 2];
                    uint4 wb = w4[half * 4 + h * 2 + 1];
                    uint32_t v0 = stc[u.x & 0xFFFFu];
                    uint32_t v1 = stc[u.x >> 16];
                    uint32_t v2 = stc[u.y & 0xFFFFu];
                    uint32_t v3 = stc[u.y >> 16];
                    uint32_t v4 = stc[u.z & 0xFFFFu];
                    uint32_t v5 = stc[u.z >> 16];
                    uint32_t v6 = stc[u.w & 0xFFFFu];
                    uint32_t v7 = stc[u.w >> 16];
                    A = __hfma2(u2h(v0), u2h(wa.x), A);
                    B = __hfma2(u2h(v1), u2h(wa.y), B);
                    C = __hfma2(u2h(v2), u2h(wa.z), C);
                    D = __hfma2(u2h(v3), u2h(wa.w), D);
                    A = __hfma2(u2h(v4), u2h(wb.x), A);
                    B = __hfma2(u2h(v5), u2h(wb.y), B);
                    C = __hfma2(u2h(v6), u2h(wb.z), C);
                    D = __hfma2(u2h(v7), u2h(wb.w), D);
                }
                __half2 s = __hadd2(__hadd2(A, B), __hadd2(C, D));
                float2  f = __half22float2(s);
                z0 += f.x;
                z1 += f.y;
            }
            float o0 = __fdividef(1.0f, 1.0f + __expf(-z0));
            float o1 = __fdividef(1.0f, 1.0f + __expf(-z1));
            __half2 hres = __floats2half2_rn(o0, o1);
            stc[tgt] = *(uint32_t*)&hres;
            buf ^= 1;
        }
        __syncthreads();                           // level boundary only
    }

    // ---- output: out[b][j] f32; 2 chunks of 32 output nodes ----
    for (int ch = 0; ch < 2; ch++) {
        const int j0 = ch * 32;
        __syncthreads();
        #pragma unroll
        for (int i = 0; i < 2; i++) {
            int idx = tid + i * THREADS;           // 1024 = 32 j x 32 words
            int j = idx >> 5, wc = idx & 31;
            uint32_t u = st[(NUM_IN + NUM_HID + j0 + j) * WPN + wc];
            float2 v = __half22float2(*(__half2*)&u);
            stage[(2 * wc) * 33 + j]     = v.x;
            stage[(2 * wc + 1) * 33 + j] = v.y;
        }
        __syncthreads();
        #pragma unroll
        for (int i = 0; i < 4; i++) {
            int idx = tid + i * THREADS;           // 2048 = 64 rows x 32 j
            int row = idx >> 5, j = idx & 31;
            out[(size_t)(b0 + row) * NUM_OUT + j0 + j] = stage[row * 33 + j];
        }
    }
}

// ---------------------------------------------------------------------------
extern "C" void kernel_launch(void* const* d_in, const int* in_sizes, int n_in,
                              void* d_out, int out_size) {
    const float* x    = (const float*)d_in[0];
    const float* w    = (const float*)d_in[1];
    const float* bias = (const float*)d_in[2];
    const int*   src  = (const int*)d_in[3];
    float* out = (float*)d_out;
    (void)in_sizes; (void)n_in; (void)out_size;

    cudaFuncSetAttribute(neat_main_kernel,
                         cudaFuncAttributeMaxDynamicSharedMemorySize,
                         TOTAL_WORDS * 4);

    schedule_kernel<<<1, M_NODES>>>(src);
    blob_fill_kernel<<<M_NODES, 64>>>(src, w, bias);
    neat_main_kernel<<<BATCH / COLS, THREADS, TOTAL_WORDS * 4>>>(x, out);
}

// round 15
// speedup vs baseline: 1.1700x; 1.0465x over previous
#include <cuda_runtime.h>
#include <cuda_fp16.h>
#include <cstdint>

#define BATCH   32768
#define NUM_IN  256
#define NUM_HID 512
#define NUM_OUT 64
#define M_NODES 576
#define N_NODES 832
#define KFAN    32
#define COLS    64             // batch columns per block (32 half2 words)
#define WPN     32             // u32 words per node row
#define THREADS 512            // 16 warps
#define SLOTS   20             // nodes per round (warps 0-3 take 2)
#define SSTRIDE 48             // words per slot: 16 src16 + 32 w_h2
#define RSTRIDE 1000           // 20*48 + 20 bias + 20 tgt
#define RMAX    576
#define DUMMY   576            // dummy pred index, level pinned 0

// round-major param blob, round r at r*RSTRIDE:
//   slot s: [s*48 .. s*48+16) src16 (two u16 pred*WPN offsets per u32)
//           [s*48+16 .. s*48+48) w_h2 (u32 = half2 {w,w})
//   [960..980) bias per slot (f32)
//   [980..1000) target word-offset per slot (int), -1 = dummy
__device__ float g_blob[(size_t)RMAX * RSTRIDE];
__device__ int   g_sched[RMAX * SLOTS];
__device__ int   g_nrounds;

// ---------------------------------------------------------------------------
// Kernel A: ASAP levels via chunked Gauss-Seidel (R11-proven), then
// counting-sort levels into rounds of <= SLOTS (=20).
// ---------------------------------------------------------------------------
__global__ __launch_bounds__(M_NODES)
void schedule_kernel(const int* __restrict__ src) {
    __shared__ int lev[DUMMY + 32];       // lev[DUMMY..] pinned 0
    __shared__ int cnt[M_NODES + 1];
    __shared__ int rbase[M_NODES + 1];
    __shared__ int pos[M_NODES + 1];
    __shared__ int lmax, R_sh;

    const int t = threadIdx.x;

    int p[KFAN];
    #pragma unroll
    for (int k = 0; k < KFAN; k++) {
        int s = src[t * KFAN + k];
        p[k] = (s >= NUM_IN) ? (s - NUM_IN) : DUMMY;
    }
    lev[t] = 0;
    if (t < 32) lev[DUMMY + t] = 0;
    for (int i = t; i <= M_NODES; i += M_NODES) { cnt[i] = 0; pos[i] = 0; }
    if (t == 0) lmax = 0;
    __syncthreads();

    for (int c = 0; c < M_NODES / 64; c++) {
        const bool mine = ((t >> 6) == c);
        while (true) {
            int ch = 0;
            if (mine) {
                int m = 0;
                #pragma unroll
                for (int k = 0; k < KFAN; k++) {
                    int l = lev[p[k]];
                    m = (l > m) ? l : m;
                }
                if (m + 1 != lev[t]) { lev[t] = m + 1; ch = 1; }
            }
            if (!__syncthreads_or(ch)) break;
        }
    }

    atomicAdd(&cnt[lev[t]], 1);
    atomicMax(&lmax, lev[t]);
    __syncthreads();

    if (t == 0) {
        int r = 0;
        for (int L = 1; L <= lmax; L++) { rbase[L] = r; r += (cnt[L] + SLOTS - 1) / SLOTS; }
        R_sh = r;
        g_nrounds = r;
    }
    __syncthreads();

    for (int i = t; i < R_sh * SLOTS; i += M_NODES) g_sched[i] = -1;
    __syncthreads();

    {
        int L = lev[t];
        int q = atomicAdd(&pos[L], 1);
        g_sched[(rbase[L] + q / SLOTS) * SLOTS + (q % SLOTS)] = t;
    }
}

// ---------------------------------------------------------------------------
// Kernel B: grid-parallel blob fill, one block per (used) round.
// ---------------------------------------------------------------------------
__global__ __launch_bounds__(256)
void blob_fill_kernel(const int* __restrict__ src,
                      const float* __restrict__ w,
                      const float* __restrict__ bias) {
    const int r = blockIdx.x;
    if (r >= g_nrounds) return;
    float* Pr = g_blob + (size_t)r * RSTRIDE;
    const int tid = threadIdx.x;

    // src16: 20 slots x 16 words = 320
    #pragma unroll
    for (int u = tid; u < SLOTS * 16; u += 256) {
        int slot = u >> 4, j = u & 15;
        int nd = g_sched[r * SLOTS + slot];
        unsigned v = 0;
        if (nd >= 0) {
            unsigned a = (unsigned)src[nd * KFAN + 2 * j] * WPN;
            unsigned b = (unsigned)src[nd * KFAN + 2 * j + 1] * WPN;
            v = (a & 0xFFFFu) | (b << 16);
        }
        ((unsigned*)Pr)[slot * SSTRIDE + j] = v;
    }
    // w_h2: 20 slots x 32 = 640
    #pragma unroll
    for (int u = tid; u < SLOTS * 32; u += 256) {
        int slot = u >> 5, k = u & 31;
        int nd = g_sched[r * SLOTS + slot];
        float wv = (nd >= 0) ? w[nd * KFAN + k] : 0.0f;
        __half2 h2 = __half2half2(__float2half_rn(wv));
        ((uint32_t*)Pr)[slot * SSTRIDE + 16 + k] = *(uint32_t*)&h2;
    }
    // bias + target
    if (tid < SLOTS) {
        int nd = g_sched[r * SLOTS + tid];
        Pr[960 + tid] = (nd >= 0) ? bias[nd] : 0.0f;
        ((int*)Pr)[980 + tid] = (nd >= 0) ? (NUM_IN + nd) * WPN : -1;
    }
}

// ---------------------------------------------------------------------------
// Main kernel: 512 blocks x 512 threads, 2 blocks/SM. SMEM footprint is
// byte-identical to R11. State half2-packed; HFMA2 inner product; params
// double-buffered via cp.async. 20-slot rounds: warp w does slot w, and
// warps 0-3 also slot 16+w.
// ---------------------------------------------------------------------------
#define ST_WORDS    (N_NODES * WPN)                // 26624 u32
#define STAGE_WORDS 2112                           // staging >= 2*RSTRIDE (2000)
#define TOTAL_WORDS (ST_WORDS + STAGE_WORDS)       // 28736 -> 114944 B (= R11)

extern __shared__ float smem_f[];

__device__ __forceinline__ void cp16(void* sdst, const void* gsrc) {
    uint32_t s = (uint32_t)__cvta_generic_to_shared(sdst);
    asm volatile("cp.async.cg.shared.global [%0], [%1], 16;\n" :: "r"(s), "l"(gsrc));
}

__device__ __forceinline__ __half2 u2h(uint32_t u) { return *(__half2*)&u; }

__device__ __forceinline__ void eval_slot(const float* P, int slot,
                                          uint32_t* stc) {
    const int tgt = ((const int*)P)[980 + slot];
    if (tgt < 0) return;
    const uint4* s4 = (const uint4*)(P + slot * SSTRIDE);
    const uint4* w4 = (const uint4*)((const uint32_t*)P + slot * SSTRIDE + 16);
    const float  bt = P[960 + slot];

    float z0 = bt, z1 = bt;
    #pragma unroll
    for (int half = 0; half < 2; half++) {         // 16 preds per flush group
        __half2 A = __float2half2_rn(0.f);
        __half2 B = __float2half2_rn(0.f);
        __half2 C = __float2half2_rn(0.f);
        __half2 D = __float2half2_rn(0.f);
        #pragma unroll
        for (int h = 0; h < 2; h++) {              // 8 preds per iter
            uint4 u  = s4[half * 2 + h];
            uint4 wa = w4[half * 4 + h * 2];
            uint4 wb = w4[half * 4 + h * 2 + 1];
            uint32_t v0 = stc[u.x & 0xFFFFu];
            uint32_t v1 = stc[u.x >> 16];
            uint32_t v2 = stc[u.y & 0xFFFFu];
            uint32_t v3 = stc[u.y >> 16];
            uint32_t v4 = stc[u.z & 0xFFFFu];
            uint32_t v5 = stc[u.z >> 16];
            uint32_t v6 = stc[u.w & 0xFFFFu];
            uint32_t v7 = stc[u.w >> 16];
            A = __hfma2(u2h(v0), u2h(wa.x), A);
            B = __hfma2(u2h(v1), u2h(wa.y), B);
            C = __hfma2(u2h(v2), u2h(wa.z), C);
            D = __hfma2(u2h(v3), u2h(wa.w), D);
            A = __hfma2(u2h(v4), u2h(wb.x), A);
            B = __hfma2(u2h(v5), u2h(wb.y), B);
            C = __hfma2(u2h(v6), u2h(wb.z), C);
            D = __hfma2(u2h(v7), u2h(wb.w), D);
        }
        __half2 s = __hadd2(__hadd2(A, B), __hadd2(C, D));
        float2  f = __half22float2(s);
        z0 += f.x;
        z1 += f.y;
    }
    float o0 = __fdividef(1.0f, 1.0f + __expf(-z0));
    float o1 = __fdividef(1.0f, 1.0f + __expf(-z1));
    __half2 hres = __floats2half2_rn(o0, o1);
    stc[tgt] = *(uint32_t*)&hres;
}

__global__ __launch_bounds__(THREADS, 2)
void neat_main_kernel(const float* __restrict__ x,
                      float* __restrict__ out) {
    uint32_t* st   = (uint32_t*)smem_f;            // [N_NODES][WPN] half2 words
    float*   stage = smem_f + ST_WORDS;            // staging / param double buffer

    const int tid  = threadIdx.x;
    const int wid  = tid >> 5;
    const int lane = tid & 31;
    const int b0   = blockIdx.x * COLS;
    const int R    = g_nrounds;

    // ---- input: x[b][n] f32 -> st[n] half2-packed; 8 chunks of 32 inputs ----
    for (int ch = 0; ch < 8; ch++) {
        const int nc0 = ch * 32;
        __syncthreads();
        #pragma unroll
        for (int i = 0; i < 4; i++) {
            int idx = tid + i * THREADS;           // 2048 = 64 rows x 32 cols
            int row = idx >> 5, c = idx & 31;
            stage[row * 33 + c] = x[(size_t)(b0 + row) * NUM_IN + nc0 + c];
        }
        __syncthreads();
        #pragma unroll
        for (int i = 0; i < 2; i++) {
            int idx = tid + i * THREADS;           // 1024 = 32 nodes x 32 words
            int n = idx >> 5, wc = idx & 31;
            float lo = stage[(2 * wc) * 33 + n];
            float hi = stage[(2 * wc + 1) * 33 + n];
            __half2 h = __floats2half2_rn(lo, hi);
            st[(nc0 + n) * WPN + wc] = *(uint32_t*)&h;
        }
    }
    __syncthreads();

    // ---- prefetch round 0 params (1000 words = 250 x 16B) ----
    if (tid < RSTRIDE / 4) cp16(stage + tid * 4, g_blob + tid * 4);
    asm volatile("cp.async.commit_group;\n");
    asm volatile("cp.async.wait_group 0;\n" ::: "memory");
    __syncthreads();

    uint32_t* stc = st + lane;                     // lane owns cols (2l, 2l+1)

    // ---- main rounds ----
    for (int r = 0; r < R; r++) {
        float* P  = stage + (r & 1) * RSTRIDE;
        float* Pn = stage + ((r + 1) & 1) * RSTRIDE;
        if (r + 1 < R && tid < RSTRIDE / 4)
            cp16(Pn + tid * 4, g_blob + (size_t)(r + 1) * RSTRIDE + tid * 4);
        asm volatile("cp.async.commit_group;\n");

        eval_slot(P, wid, stc);
        if (wid < SLOTS - 16) eval_slot(P, 16 + wid, stc);

        asm volatile("cp.async.wait_group 0;\n" ::: "memory");
        __syncthreads();
    }

    // ---- output: out[b][j] f32; 2 chunks of 32 output nodes ----
    for (int ch = 0; ch < 2; ch++) {
        const int j0 = ch * 32;
        __syncthreads();
        #pragma unroll
        for (int i = 0; i < 2; i++) {
            int idx = tid + i * THREADS;           // 1024 = 32 j x 32 words
            int j = idx >> 5, wc = idx & 31;
            uint32_t u = st[(NUM_IN + NUM_HID + j0 + j) * WPN + wc];
            float2 v = __half22float2(*(__half2*)&u);
            stage[(2 * wc) * 33 + j]     = v.x;
            stage[(2 * wc + 1) * 33 + j] = v.y;
        }
        __syncthreads();
        #pragma unroll
        for (int i = 0; i < 4; i++) {
            int idx = tid + i * THREADS;           // 2048 = 64 rows x 32 j
            int row = idx >> 5, j = idx & 31;
            out[(size_t)(b0 + row) * NUM_OUT + j0 + j] = stage[row * 33 + j];
        }
    }
}

// ---------------------------------------------------------------------------
extern "C" void kernel_launch(void* const* d_in, const int* in_sizes, int n_in,
                              void* d_out, int out_size) {
    const float* x    = (const float*)d_in[0];
    const float* w    = (const float*)d_in[1];
    const float* bias = (const float*)d_in[2];
    const int*   src  = (const int*)d_in[3];
    float* out = (float*)d_out;
    (void)in_sizes; (void)n_in; (void)out_size;

    cudaFuncSetAttribute(neat_main_kernel,
                         cudaFuncAttributeMaxDynamicSharedMemorySize,
                         TOTAL_WORDS * 4);

    schedule_kernel<<<1, M_NODES>>>(src);
    blob_fill_kernel<<<RMAX, 256>>>(src, w, bias);
    neat_main_kernel<<<BATCH / COLS, THREADS, TOTAL_WORDS * 4>>>(x, out);
}